// round 1
// baseline (speedup 1.0000x reference)
#include <cuda_runtime.h>
#include <cuda_bf16.h>
#include <cstdint>

// Problem constants
#define N_TOKENS 8192
#define D_MODEL  4096
#define N_EXPERTS 256
#define N_GROUP 4
#define GROUP_SIZE 64
#define TOPK_GROUP 2
#define TOPK_TOTAL 8   // N_GROUP * TOPK_GROUP

// GEMM tiling
#define BM 128
#define BN 64
#define BK 16
#define TM 8
#define TN 4
// threads = (BM/TM) * (BN/TN) = 16*16 = 256

// C[m,n] = sum_k H[m,k] * W[n,k]
// H: [N_TOKENS, D_MODEL] row-major, W: [N_EXPERTS, D_MODEL] row-major
__global__ __launch_bounds__(256) void moe_gemm_kernel(
    const float* __restrict__ H,
    const float* __restrict__ W,
    float* __restrict__ out_logits)
{
    __shared__ float As[BK][BM];   // transposed H tile
    __shared__ float Bs[BK][BN];   // transposed W tile

    const int bm = blockIdx.y * BM;
    const int bn = blockIdx.x * BN;
    const int tid = threadIdx.x;
    const int tx = tid & 15;   // N direction, TN=4
    const int ty = tid >> 4;   // M direction, TM=8

    float acc[TM][TN];
#pragma unroll
    for (int i = 0; i < TM; i++)
#pragma unroll
        for (int j = 0; j < TN; j++)
            acc[i][j] = 0.f;

    for (int k0 = 0; k0 < D_MODEL; k0 += BK) {
        // Load H tile: 128 rows x 16 cols = 512 float4, 2 per thread
#pragma unroll
        for (int i = 0; i < 2; i++) {
            int v   = tid + i * 256;   // 0..511
            int row = v >> 2;          // 0..127
            int c4  = v & 3;           // 0..3
            float4 h = *reinterpret_cast<const float4*>(
                &H[(size_t)(bm + row) * D_MODEL + k0 + c4 * 4]);
            As[c4 * 4 + 0][row] = h.x;
            As[c4 * 4 + 1][row] = h.y;
            As[c4 * 4 + 2][row] = h.z;
            As[c4 * 4 + 3][row] = h.w;
        }
        // Load W tile: 64 rows x 16 cols = 256 float4, 1 per thread
        {
            int row = tid >> 2;   // 0..63
            int c4  = tid & 3;    // 0..3
            float4 w = *reinterpret_cast<const float4*>(
                &W[(size_t)(bn + row) * D_MODEL + k0 + c4 * 4]);
            Bs[c4 * 4 + 0][row] = w.x;
            Bs[c4 * 4 + 1][row] = w.y;
            Bs[c4 * 4 + 2][row] = w.z;
            Bs[c4 * 4 + 3][row] = w.w;
        }
        __syncthreads();

#pragma unroll
        for (int k = 0; k < BK; k++) {
            float4 a0 = *reinterpret_cast<const float4*>(&As[k][ty * TM]);
            float4 a1 = *reinterpret_cast<const float4*>(&As[k][ty * TM + 4]);
            float4 bb = *reinterpret_cast<const float4*>(&Bs[k][tx * TN]);
            float a[TM] = {a0.x, a0.y, a0.z, a0.w, a1.x, a1.y, a1.z, a1.w};
            float b[TN] = {bb.x, bb.y, bb.z, bb.w};
#pragma unroll
            for (int i = 0; i < TM; i++)
#pragma unroll
                for (int j = 0; j < TN; j++)
                    acc[i][j] = fmaf(a[i], b[j], acc[i][j]);
        }
        __syncthreads();
    }

    // Epilogue: write logits
#pragma unroll
    for (int i = 0; i < TM; i++) {
        int m = bm + ty * TM + i;
        float4 v0 = make_float4(acc[i][0], acc[i][1], acc[i][2], acc[i][3]);
        *reinterpret_cast<float4*>(&out_logits[(size_t)m * N_EXPERTS + bn + tx * TN]) = v0;
    }
}

// One warp per token: sigmoid scores, top-2 within each of 4 groups of 64,
// normalize the 8 weights, scale by 2.5. idx written as float.
__global__ __launch_bounds__(256) void moe_topk_kernel(
    const float* __restrict__ logits,
    float* __restrict__ out_idx,
    float* __restrict__ out_w)
{
    __shared__ float sc[8][N_EXPERTS];
    __shared__ float bval[8][TOPK_TOTAL];
    __shared__ int   bidx[8][TOPK_TOTAL];

    const int warp = threadIdx.x >> 5;
    const int lane = threadIdx.x & 31;
    const int t = blockIdx.x * 8 + warp;

    const float* lg = logits + (size_t)t * N_EXPERTS;
#pragma unroll
    for (int i = 0; i < N_EXPERTS / 32; i++) {
        float x = lg[lane + i * 32];
        sc[warp][lane + i * 32] = 1.f / (1.f + __expf(-x));
    }
    __syncwarp();

    if (lane < N_GROUP) {
        const int g = lane;
        float b1 = -1.f, b2 = -1.f;
        int i1 = 0, i2 = 0;
#pragma unroll 4
        for (int j = 0; j < GROUP_SIZE; j++) {
            float s = sc[warp][g * GROUP_SIZE + j];
            if (s > b1) { b2 = b1; i2 = i1; b1 = s; i1 = j; }
            else if (s > b2) { b2 = s; i2 = j; }
        }
        bval[warp][g * 2]     = b1; bidx[warp][g * 2]     = g * GROUP_SIZE + i1;
        bval[warp][g * 2 + 1] = b2; bidx[warp][g * 2 + 1] = g * GROUP_SIZE + i2;
    }
    __syncwarp();

    if (lane == 0) {
        float sum = 0.f;
#pragma unroll
        for (int j = 0; j < TOPK_TOTAL; j++) sum += bval[warp][j];
        float scale = 2.5f / (sum + 1e-10f);
#pragma unroll
        for (int j = 0; j < TOPK_TOTAL; j++) {
            out_idx[(size_t)t * TOPK_TOTAL + j] = (float)bidx[warp][j];
            out_w[(size_t)t * TOPK_TOTAL + j]   = bval[warp][j] * scale;
        }
    }
}

extern "C" void kernel_launch(void* const* d_in, const int* in_sizes, int n_in,
                              void* d_out, int out_size)
{
    const float* H = (const float*)d_in[0];   // hidden_states [8192, 4096]
    const float* W = (const float*)d_in[1];   // gate_w        [256, 4096]
    float* out = (float*)d_out;

    // Output layout: topk_idx [8192*8] | topk_weight [8192*8] | gate_logits [8192*256]
    float* out_idx    = out;
    float* out_w      = out + (size_t)N_TOKENS * TOPK_TOTAL;
    float* out_logits = out + (size_t)N_TOKENS * TOPK_TOTAL * 2;

    dim3 grid(N_EXPERTS / BN, N_TOKENS / BM);  // (4, 64)
    moe_gemm_kernel<<<grid, 256>>>(H, W, out_logits);
    moe_topk_kernel<<<N_TOKENS / 8, 256>>>(out_logits, out_idx, out_w);
}

// round 5
// speedup vs baseline: 1.5611x; 1.5611x over previous
#include <cuda_runtime.h>
#include <cuda_bf16.h>
#include <cstdint>

#define N_TOKENS 8192
#define D_MODEL  4096
#define N_EXPERTS 256
#define N_GROUP 4
#define GROUP_SIZE 64
#define TOPK_TOTAL 8

#define BM 64
#define BN 256
#define BK 64
#define NCHUNK (D_MODEL / BK)   // 64
#define THREADS 512             // 16 warps, warp tile 16x64 (4 m-tiles x 4 n-groups)

// smem stage layout (bytes): Ahi[64*128] Alo[64*128] Bhi[256*128] Blo[256*128]
#define AHI 0
#define ALO 8192
#define BHI 16384
#define BLO 49152
#define STAGE_BYTES 81920
#define SMEM_TOTAL (2 * STAGE_BYTES)   // 163840

__device__ __forceinline__ uint32_t smem_u32(const void* p) {
    uint32_t a;
    asm("{ .reg .u64 t; cvta.to.shared.u64 t, %1; cvt.u32.u64 %0, t; }" : "=r"(a) : "l"(p));
    return a;
}

__device__ __forceinline__ void ldsm4(uint32_t (&r)[4], uint32_t addr) {
    asm volatile("ldmatrix.sync.aligned.m8n8.x4.shared.b16 {%0,%1,%2,%3}, [%4];"
                 : "=r"(r[0]), "=r"(r[1]), "=r"(r[2]), "=r"(r[3]) : "r"(addr));
}

__device__ __forceinline__ void mma16816(float (&c)[4], const uint32_t (&a)[4],
                                         uint32_t b0, uint32_t b1) {
    asm volatile("mma.sync.aligned.m16n8k16.row.col.f32.bf16.bf16.f32 "
                 "{%0,%1,%2,%3}, {%4,%5,%6,%7}, {%8,%9}, {%0,%1,%2,%3};"
                 : "+f"(c[0]), "+f"(c[1]), "+f"(c[2]), "+f"(c[3])
                 : "r"(a[0]), "r"(a[1]), "r"(a[2]), "r"(a[3]), "r"(b0), "r"(b1));
}

// pack (x,y) into bf16x2 hi (rn) and bf16x2 lo (residual, rn)
__device__ __forceinline__ void pack_hilo(float x, float y, uint32_t& hi, uint32_t& lo) {
    asm("cvt.rn.bf16x2.f32 %0, %1, %2;" : "=r"(hi) : "f"(y), "f"(x));
    float hx = __uint_as_float(hi << 16);
    float hy = __uint_as_float(hi & 0xFFFF0000u);
    asm("cvt.rn.bf16x2.f32 %0, %1, %2;" : "=r"(lo) : "f"(y - hy), "f"(x - hx));
}

__device__ __forceinline__ void split_sts(char* base, uint32_t off, float4 v) {
    uint2 hi, lo;
    pack_hilo(v.x, v.y, hi.x, lo.x);
    pack_hilo(v.z, v.w, hi.y, lo.y);
    *(uint2*)(base + AHI + off) = hi;   // caller passes A/B-specific base; ALO-AHI == 8192 for A,
    *(uint2*)(base + 8192 + off) = lo;  // BLO-BHI == 32768 handled by caller via base choice
}

__global__ __launch_bounds__(THREADS, 1) void moe_fused_kernel(
    const float* __restrict__ H,
    const float* __restrict__ W,
    float* __restrict__ out_idx,
    float* __restrict__ out_w,
    float* __restrict__ out_logits)
{
    extern __shared__ char smem[];
    __shared__ float s_bv[BM][TOPK_TOTAL];
    __shared__ int   s_bi[BM][TOPK_TOTAL];

    const uint32_t sb = smem_u32(smem);
    const int tid  = threadIdx.x;
    const int wid  = tid >> 5;
    const int lane = tid & 31;
    const int bm   = blockIdx.x * BM;

    // warp tile
    const int mw    = wid & 3;          // m-tile 0..3 (16 rows each)
    const int nbase = (wid >> 2) * 64;  // n-group 0..3 (64 cols each)

    // loader mapping
    const int arow = tid >> 3;               // 0..63, 8 thr/row
    const int acol = (tid & 7) * 8;          // float index in row (2 float4)
    const int brow = tid >> 1;               // 0..255, 2 thr/row
    const int bcol = (tid & 1) * 32;         // float index (8 float4)

    const float* hp = H + (size_t)(bm + arow) * D_MODEL + acol;
    const float* wp = W + (size_t)brow * D_MODEL + bcol;

    // swizzled STS byte offsets (within 128B rows): off = row*128 + (2*f ^ ((row&7)<<4))
    const uint32_t axor = (uint32_t)(arow & 7) << 4;
    const uint32_t bxor = (uint32_t)(brow & 7) << 4;

    float acc[8][4];
#pragma unroll
    for (int i = 0; i < 8; i++)
#pragma unroll
        for (int j = 0; j < 4; j++) acc[i][j] = 0.f;

    // prefetch chunk 0
    float4 ha[2], wb[8];
#pragma unroll
    for (int j = 0; j < 2; j++) ha[j] = *(const float4*)(hp + j * 4);
#pragma unroll
    for (int j = 0; j < 8; j++) wb[j] = *(const float4*)(wp + j * 4);

    for (int c = 0; c < NCHUNK; c++) {
        char* stage = smem + (c & 1) * STAGE_BYTES;
        // convert + store A
#pragma unroll
        for (int j = 0; j < 2; j++) {
            uint32_t off = (uint32_t)arow * 128 + (((uint32_t)(acol + j * 4) * 2) ^ axor);
            split_sts(stage, off, ha[j]);   // writes AHI+off and ALO+off
        }
        // convert + store B
#pragma unroll
        for (int j = 0; j < 8; j++) {
            uint32_t off = (uint32_t)brow * 128 + (((uint32_t)(bcol + j * 4) * 2) ^ bxor);
            uint2 hi, lo;
            pack_hilo(wb[j].x, wb[j].y, hi.x, lo.x);
            pack_hilo(wb[j].z, wb[j].w, hi.y, lo.y);
            *(uint2*)(stage + BHI + off) = hi;
            *(uint2*)(stage + BLO + off) = lo;
        }
        // prefetch next chunk (latency hidden under MMA section)
        if (c + 1 < NCHUNK) {
            const float* hn = hp + (c + 1) * BK;
            const float* wn = wp + (c + 1) * BK;
#pragma unroll
            for (int j = 0; j < 2; j++) ha[j] = *(const float4*)(hn + j * 4);
#pragma unroll
            for (int j = 0; j < 8; j++) wb[j] = *(const float4*)(wn + j * 4);
        }
        __syncthreads();

        // MMA section
        const uint32_t stg = sb + (c & 1) * STAGE_BYTES;
        const int mrow = mw * 16 + (lane & 15);
        const uint32_t a_base = stg + AHI + (uint32_t)mrow * 128;
        const uint32_t a_xor  = (uint32_t)(mrow & 7) << 4;
#pragma unroll
        for (int k16 = 0; k16 < 4; k16++) {
            const uint32_t cb = (uint32_t)k16 * 32 + ((lane >> 4) << 4);
            uint32_t ahf[4], alf[4];
            uint32_t aaddr = a_base + (cb ^ a_xor);
            ldsm4(ahf, aaddr);
            ldsm4(alf, aaddr + (ALO - AHI));
#pragma unroll
            for (int nf2 = 0; nf2 < 4; nf2++) {
                const int nrow = nbase + nf2 * 16 + (lane & 15);
                uint32_t baddr = stg + BHI + (uint32_t)nrow * 128
                               + (cb ^ ((uint32_t)(nrow & 7) << 4));
                uint32_t bhf[4], blf[4];
                ldsm4(bhf, baddr);
                ldsm4(blf, baddr + (BLO - BHI));
                mma16816(acc[nf2 * 2 + 0], ahf, bhf[0], bhf[2]);
                mma16816(acc[nf2 * 2 + 1], ahf, bhf[1], bhf[3]);
                mma16816(acc[nf2 * 2 + 0], ahf, blf[0], blf[2]);
                mma16816(acc[nf2 * 2 + 1], ahf, blf[1], blf[3]);
                mma16816(acc[nf2 * 2 + 0], alf, bhf[0], bhf[2]);
                mma16816(acc[nf2 * 2 + 1], alf, bhf[1], bhf[3]);
            }
        }
    }

    // ---- epilogue: write logits to gmem, sigmoid scores to smem ----
    float* sc = (float*)smem;   // sc[m][n], stride 256 floats (reuses stage 0; last chunk used stage 1)
    const int m0  = mw * 16 + (lane >> 2);
    const int cl0 = 2 * (lane & 3);
#pragma unroll
    for (int nf = 0; nf < 8; nf++) {
        const int col = nbase + nf * 8 + cl0;
        float c0 = acc[nf][0], c1 = acc[nf][1], c2 = acc[nf][2], c3 = acc[nf][3];
        *(float2*)&out_logits[(size_t)(bm + m0) * N_EXPERTS + col]     = make_float2(c0, c1);
        *(float2*)&out_logits[(size_t)(bm + m0 + 8) * N_EXPERTS + col] = make_float2(c2, c3);
        float s0 = 1.f / (1.f + __expf(-c0));
        float s1 = 1.f / (1.f + __expf(-c1));
        float s2 = 1.f / (1.f + __expf(-c2));
        float s3 = 1.f / (1.f + __expf(-c3));
        *(float2*)&sc[(size_t)m0 * N_EXPERTS + col]       = make_float2(s0, s1);
        *(float2*)&sc[(size_t)(m0 + 8) * N_EXPERTS + col] = make_float2(s2, s3);
    }
    __syncthreads();

    // ---- fused top-k: 16 warps x 4 tokens each ----
#pragma unroll
    for (int i = 0; i < 4; i++) {
        const int tk = wid * 4 + i;
        if (lane < N_GROUP) {
            const int g = lane;
            const float* row = sc + (size_t)tk * N_EXPERTS + g * GROUP_SIZE;
            float b1 = -1.f, b2 = -1.f;
            int i1 = 0, i2 = 0;
#pragma unroll 4
            for (int j = 0; j < GROUP_SIZE; j++) {
                float s = row[j];
                if (s > b1) { b2 = b1; i2 = i1; b1 = s; i1 = j; }
                else if (s > b2) { b2 = s; i2 = j; }
            }
            s_bv[tk][g * 2]     = b1; s_bi[tk][g * 2]     = g * GROUP_SIZE + i1;
            s_bv[tk][g * 2 + 1] = b2; s_bi[tk][g * 2 + 1] = g * GROUP_SIZE + i2;
        }
        __syncwarp();
        if (lane == 0) {
            float sum = 0.f;
#pragma unroll
            for (int j = 0; j < TOPK_TOTAL; j++) sum += s_bv[tk][j];
            const float scale = 2.5f / (sum + 1e-10f);
            const size_t orow = (size_t)(bm + tk) * TOPK_TOTAL;
#pragma unroll
            for (int j = 0; j < TOPK_TOTAL; j++) {
                out_idx[orow + j] = (float)s_bi[tk][j];
                out_w[orow + j]   = s_bv[tk][j] * scale;
            }
        }
        __syncwarp();
    }
}

extern "C" void kernel_launch(void* const* d_in, const int* in_sizes, int n_in,
                              void* d_out, int out_size)
{
    const float* H = (const float*)d_in[0];   // [8192, 4096]
    const float* W = (const float*)d_in[1];   // [256, 4096]
    float* out = (float*)d_out;

    float* out_idx    = out;
    float* out_w      = out + (size_t)N_TOKENS * TOPK_TOTAL;
    float* out_logits = out + (size_t)N_TOKENS * TOPK_TOTAL * 2;

    static int configured = 0;
    if (!configured) {
        cudaFuncSetAttribute(moe_fused_kernel,
                             cudaFuncAttributeMaxDynamicSharedMemorySize, SMEM_TOTAL);
        configured = 1;
    }
    moe_fused_kernel<<<N_TOKENS / BM, THREADS, SMEM_TOTAL>>>(H, W, out_idx, out_w, out_logits);
}

// round 8
// speedup vs baseline: 2.0139x; 1.2900x over previous
#include <cuda_runtime.h>
#include <cuda_bf16.h>
#include <cstdint>

#define N_TOKENS 8192
#define D_MODEL  4096
#define N_EXPERTS 256
#define N_GROUP 4
#define GROUP_SIZE 64
#define TOPK_TOTAL 8

#define BM 64
#define BN 256
#define BK 64
#define NCHUNK (D_MODEL / BK)   // 64
#define THREADS 512             // 8 consumer warps + 8 producer warps

// stage layout (bytes): Ahi[64*128] Alo Bhi[256*128] Blo
#define AHI 0
#define ALO 8192
#define BHI 16384
#define BLO 49152
#define STAGE_BYTES 81920
#define STAGE_OFF 1024
#define SMEM_TOTAL (STAGE_OFF + 2 * STAGE_BYTES)   // 164864

// pre-split W (bf16 hi/lo), 2MB each
__device__ __nv_bfloat16 g_whi[N_EXPERTS * D_MODEL];
__device__ __nv_bfloat16 g_wlo[N_EXPERTS * D_MODEL];

__device__ __forceinline__ uint32_t smem_u32(const void* p) {
    uint32_t a;
    asm("{ .reg .u64 t; cvta.to.shared.u64 t, %1; cvt.u32.u64 %0, t; }" : "=r"(a) : "l"(p));
    return a;
}
__device__ __forceinline__ void mbar_init(uint32_t m, uint32_t cnt) {
    asm volatile("mbarrier.init.shared.b64 [%0], %1;" :: "r"(m), "r"(cnt) : "memory");
}
__device__ __forceinline__ void mbar_wait(uint32_t m, int parity) {
    asm volatile(
        "{\n\t.reg .pred P;\n\t"
        "WL_%=:\n\t"
        "mbarrier.try_wait.parity.acquire.cta.shared::cta.b64 P, [%0], %1;\n\t"
        "@!P bra WL_%=;\n\t}"
        :: "r"(m), "r"(parity) : "memory");
}
__device__ __forceinline__ void mbar_arrive(uint32_t m) {
    asm volatile("mbarrier.arrive.shared.b64 _, [%0];" :: "r"(m) : "memory");
}
__device__ __forceinline__ void cp16(uint32_t dst, const void* src) {
    asm volatile("cp.async.cg.shared.global [%0], [%1], 16;" :: "r"(dst), "l"(src) : "memory");
}
__device__ __forceinline__ void ldsm4(uint32_t (&r)[4], uint32_t addr) {
    asm volatile("ldmatrix.sync.aligned.m8n8.x4.shared.b16 {%0,%1,%2,%3}, [%4];"
                 : "=r"(r[0]), "=r"(r[1]), "=r"(r[2]), "=r"(r[3]) : "r"(addr));
}
__device__ __forceinline__ void mma16816(float (&c)[4], const uint32_t (&a)[4],
                                         uint32_t b0, uint32_t b1) {
    asm volatile("mma.sync.aligned.m16n8k16.row.col.f32.bf16.bf16.f32 "
                 "{%0,%1,%2,%3}, {%4,%5,%6,%7}, {%8,%9}, {%0,%1,%2,%3};"
                 : "+f"(c[0]), "+f"(c[1]), "+f"(c[2]), "+f"(c[3])
                 : "r"(a[0]), "r"(a[1]), "r"(a[2]), "r"(a[3]), "r"(b0), "r"(b1));
}
__device__ __forceinline__ void pack_hilo(float x, float y, uint32_t& hi, uint32_t& lo) {
    asm("cvt.rn.bf16x2.f32 %0, %1, %2;" : "=r"(hi) : "f"(y), "f"(x));
    float hx = __uint_as_float(hi << 16);
    float hy = __uint_as_float(hi & 0xFFFF0000u);
    asm("cvt.rn.bf16x2.f32 %0, %1, %2;" : "=r"(lo) : "f"(y - hy), "f"(x - hx));
}

// ---- kernel 0: split W fp32 -> bf16 hi/lo ----
__global__ __launch_bounds__(256) void split_w_kernel(const float* __restrict__ W) {
    size_t i = ((size_t)blockIdx.x * 256 + threadIdx.x) * 4;
    float4 v = *(const float4*)(W + i);
    uint2 hi, lo;
    pack_hilo(v.x, v.y, hi.x, lo.x);
    pack_hilo(v.z, v.w, hi.y, lo.y);
    *(uint2*)(g_whi + i) = hi;
    *(uint2*)(g_wlo + i) = lo;
}

// ---- kernel 1: fused GEMM (warp-specialized) + topk ----
__global__ __launch_bounds__(THREADS, 1) void moe_fused_kernel(
    const float* __restrict__ H,
    float* __restrict__ out_idx,
    float* __restrict__ out_w,
    float* __restrict__ out_logits)
{
    extern __shared__ char smem[];
    __shared__ float s_bv[BM][TOPK_TOTAL];
    __shared__ int   s_bi[BM][TOPK_TOTAL];

    const uint32_t sb = smem_u32(smem);
    const int tid  = threadIdx.x;
    const int wid  = tid >> 5;
    const int lane = tid & 31;
    const int bm   = blockIdx.x * BM;

    // mbarriers: full0@0 full1@8 empty0@16 empty1@24
    if (tid == 0) {
        mbar_init(sb + 0, 256);  mbar_init(sb + 8, 256);
        mbar_init(sb + 16, 256); mbar_init(sb + 24, 256);
    }
    __syncthreads();

    float acc[2][8][4];
#pragma unroll
    for (int a = 0; a < 2; a++)
#pragma unroll
        for (int b = 0; b < 8; b++)
#pragma unroll
            for (int c = 0; c < 4; c++) acc[a][b][c] = 0.f;

    if (wid < 8) {
        // ================= CONSUMER =================
        const int mset = (wid & 1) * 32;
        const int ng   = (wid >> 1) * 64;
        int ph[2] = {0, 0};

        for (int c = 0; c < NCHUNK; c++) {
            const int s = c & 1;
            mbar_wait(sb + s * 8, ph[s]); ph[s] ^= 1;
            const uint32_t stg = sb + STAGE_OFF + s * STAGE_BYTES;
#pragma unroll
            for (int k16 = 0; k16 < 4; k16++) {
                const uint32_t cb = (uint32_t)k16 * 32 + ((lane >> 4) << 4);
                uint32_t ah[2][4], al[2][4];
#pragma unroll
                for (int mt = 0; mt < 2; mt++) {
                    const int mrow = mset + mt * 16 + (lane & 15);
                    uint32_t a = stg + AHI + (uint32_t)mrow * 128
                               + (cb ^ ((uint32_t)(mrow & 7) << 4));
                    ldsm4(ah[mt], a);
                    ldsm4(al[mt], a + (ALO - AHI));
                }
#pragma unroll
                for (int n16 = 0; n16 < 4; n16++) {
                    const int nrow = ng + n16 * 16 + (lane & 15);
                    uint32_t b = stg + BHI + (uint32_t)nrow * 128
                               + (cb ^ ((uint32_t)(nrow & 7) << 4));
                    uint32_t bh[4], bl[4];
                    ldsm4(bh, b);
                    ldsm4(bl, b + (BLO - BHI));
                    // hi*hi
#pragma unroll
                    for (int mt = 0; mt < 2; mt++) {
                        mma16816(acc[mt][n16 * 2 + 0], ah[mt], bh[0], bh[2]);
                        mma16816(acc[mt][n16 * 2 + 1], ah[mt], bh[1], bh[3]);
                    }
                    // hi*lo
#pragma unroll
                    for (int mt = 0; mt < 2; mt++) {
                        mma16816(acc[mt][n16 * 2 + 0], ah[mt], bl[0], bl[2]);
                        mma16816(acc[mt][n16 * 2 + 1], ah[mt], bl[1], bl[3]);
                    }
                    // lo*hi
#pragma unroll
                    for (int mt = 0; mt < 2; mt++) {
                        mma16816(acc[mt][n16 * 2 + 0], al[mt], bh[0], bh[2]);
                        mma16816(acc[mt][n16 * 2 + 1], al[mt], bh[1], bh[3]);
                    }
                }
            }
            mbar_arrive(sb + 16 + s * 8);
        }
    } else {
        // ================= PRODUCER =================
        const int pt = tid - 256;                 // 0..255
        const int arow = pt >> 2;                 // 0..63
        const int acol = (pt & 3) * 16;           // float index
        const uint32_t axor = (uint32_t)(arow & 7) << 4;
        const float* hp = H + (size_t)(bm + arow) * D_MODEL + acol;
        const int brow = pt;                      // 0..255
        const uint32_t bxor = (uint32_t)(brow & 7) << 4;
        const __nv_bfloat16* whp = g_whi + (size_t)brow * D_MODEL;
        const __nv_bfloat16* wlp = g_wlo + (size_t)brow * D_MODEL;
        int ph[2] = {0, 0};

        float4 ha[4];
#pragma unroll
        for (int j = 0; j < 4; j++) ha[j] = *(const float4*)(hp + j * 4);

        for (int c = 0; c < NCHUNK; c++) {
            const int s = c & 1;
            if (c >= 2) { mbar_wait(sb + 16 + s * 8, ph[s]); ph[s] ^= 1; }
            char* stage = smem + STAGE_OFF + s * STAGE_BYTES;
            const uint32_t stg = sb + STAGE_OFF + s * STAGE_BYTES;
            // A convert + STS
#pragma unroll
            for (int j = 0; j < 4; j++) {
                uint32_t off = (uint32_t)arow * 128
                             + (((uint32_t)(acol + j * 4) * 2) ^ axor);
                uint2 hi, lo;
                pack_hilo(ha[j].x, ha[j].y, hi.x, lo.x);
                pack_hilo(ha[j].z, ha[j].w, hi.y, lo.y);
                *(uint2*)(stage + AHI + off) = hi;
                *(uint2*)(stage + ALO + off) = lo;
            }
            // prefetch next A chunk
            if (c + 1 < NCHUNK) {
                const float* hn = hp + (c + 1) * BK;
#pragma unroll
                for (int j = 0; j < 4; j++) ha[j] = *(const float4*)(hn + j * 4);
            }
            // B via cp.async (pre-split bf16): one 128B row hi + one lo per thread
            const uint32_t bdh = stg + BHI + (uint32_t)brow * 128;
#pragma unroll
            for (int j = 0; j < 8; j++) {
                uint32_t sw = ((uint32_t)j * 16) ^ bxor;
                cp16(bdh + sw, whp + c * BK + j * 8);
                cp16(bdh + (BLO - BHI) + sw, wlp + c * BK + j * 8);
            }
            asm volatile("cp.async.commit_group;" ::: "memory");
            asm volatile("cp.async.wait_group 0;" ::: "memory");
            mbar_arrive(sb + s * 8);
        }
    }

    __syncthreads();

    // ---- epilogue: consumers write logits + sigmoid scores to smem ----
    float* sc = (float*)(smem + STAGE_OFF);   // [64][256]
    if (wid < 8) {
        const int mset = (wid & 1) * 32;
        const int ng   = (wid >> 1) * 64;
        const int cl0  = 2 * (lane & 3);
#pragma unroll
        for (int mt = 0; mt < 2; mt++) {
            const int m0 = mset + mt * 16 + (lane >> 2);
#pragma unroll
            for (int nf = 0; nf < 8; nf++) {
                const int col = ng + nf * 8 + cl0;
                float c0 = acc[mt][nf][0], c1 = acc[mt][nf][1];
                float c2 = acc[mt][nf][2], c3 = acc[mt][nf][3];
                *(float2*)&out_logits[(size_t)(bm + m0) * N_EXPERTS + col]     = make_float2(c0, c1);
                *(float2*)&out_logits[(size_t)(bm + m0 + 8) * N_EXPERTS + col] = make_float2(c2, c3);
                float s0 = 1.f / (1.f + __expf(-c0));
                float s1 = 1.f / (1.f + __expf(-c1));
                float s2 = 1.f / (1.f + __expf(-c2));
                float s3 = 1.f / (1.f + __expf(-c3));
                *(float2*)&sc[(size_t)m0 * N_EXPERTS + col]       = make_float2(s0, s1);
                *(float2*)&sc[(size_t)(m0 + 8) * N_EXPERTS + col] = make_float2(s2, s3);
            }
        }
    }
    __syncthreads();

    // ---- fused top-k: 16 warps x 4 tokens ----
#pragma unroll
    for (int i = 0; i < 4; i++) {
        const int tk = wid * 4 + i;
        if (lane < N_GROUP) {
            const int g = lane;
            const float* row = sc + (size_t)tk * N_EXPERTS + g * GROUP_SIZE;
            float b1 = -1.f, b2 = -1.f;
            int i1 = 0, i2 = 0;
#pragma unroll 4
            for (int j = 0; j < GROUP_SIZE; j++) {
                float s = row[j];
                if (s > b1) { b2 = b1; i2 = i1; b1 = s; i1 = j; }
                else if (s > b2) { b2 = s; i2 = j; }
            }
            s_bv[tk][g * 2]     = b1; s_bi[tk][g * 2]     = g * GROUP_SIZE + i1;
            s_bv[tk][g * 2 + 1] = b2; s_bi[tk][g * 2 + 1] = g * GROUP_SIZE + i2;
        }
        __syncwarp();
        if (lane == 0) {
            float sum = 0.f;
#pragma unroll
            for (int j = 0; j < TOPK_TOTAL; j++) sum += s_bv[tk][j];
            const float scale = 2.5f / (sum + 1e-10f);
            const size_t orow = (size_t)(bm + tk) * TOPK_TOTAL;
#pragma unroll
            for (int j = 0; j < TOPK_TOTAL; j++) {
                out_idx[orow + j] = (float)s_bi[tk][j];
                out_w[orow + j]   = s_bv[tk][j] * scale;
            }
        }
        __syncwarp();
    }
}

extern "C" void kernel_launch(void* const* d_in, const int* in_sizes, int n_in,
                              void* d_out, int out_size)
{
    const float* H = (const float*)d_in[0];   // [8192, 4096]
    const float* W = (const float*)d_in[1];   // [256, 4096]
    float* out = (float*)d_out;

    float* out_idx    = out;
    float* out_w      = out + (size_t)N_TOKENS * TOPK_TOTAL;
    float* out_logits = out + (size_t)N_TOKENS * TOPK_TOTAL * 2;

    static int configured = 0;
    if (!configured) {
        cudaFuncSetAttribute(moe_fused_kernel,
                             cudaFuncAttributeMaxDynamicSharedMemorySize, SMEM_TOTAL);
        configured = 1;
    }
    split_w_kernel<<<(N_EXPERTS * D_MODEL / 4) / 256, 256>>>(W);
    moe_fused_kernel<<<N_TOKENS / BM, THREADS, SMEM_TOTAL>>>(H, out_idx, out_w, out_logits);
}